// round 13
// baseline (speedup 1.0000x reference)
#include <cuda_runtime.h>
#include <cuda_bf16.h>
#include <cstdint>

// Problem constants
#define G    2050
#define N    2048
#define BSZ  16
#define H2   (0.00048828125f * 0.00048828125f)   // 2^-22

// Block shape: one warp spans full tile width, 8 cells per lane (two float4s)
#define IX   256             // 32 lanes x 8 floats
#define TPY  12
#define RPT  4               // rows per thread
#define IY   (TPY*RPT)       // 48
#define NTHR (32*TPY)        // 384

// Heavy-pass geometry
#define HXA  8
#define HYA  8
#define TXA  (IX - 2*HXA)    // 240
#define TYA  (IY - 2*HYA)    // 32
#define NBXA ((N + TXA - 1)/TXA)   // 9
#define NBYA ((N + TYA - 1)/TYA)   // 64

// Dynamic smem: topP[2][TPY][IX] + botP[2][TPY][IX] floats
#define SMEM_BYTES (2 * 2 * TPY * IX * 4)   // 49152

// Scratch (static device arrays; no runtime allocation)
__device__ float         g_w [(size_t)BSZ * N * N];
__device__ __nv_bfloat16 g_fq[(size_t)BSZ * N * N];   // bf16(h2 * f * 0.25)

// ---------------- packed f32x2 helpers (Blackwell) ----------------
__device__ __forceinline__ uint64_t pk2(float lo, float hi) {
    uint64_t r; asm("mov.b64 %0, {%1, %2};" : "=l"(r) : "f"(lo), "f"(hi)); return r;
}
__device__ __forceinline__ uint64_t add2(uint64_t a, uint64_t b) {
    uint64_t r; asm("add.rn.f32x2 %0, %1, %2;" : "=l"(r) : "l"(a), "l"(b)); return r;
}
__device__ __forceinline__ uint64_t fma2(uint64_t a, uint64_t b, uint64_t c) {
    uint64_t r; asm("fma.rn.f32x2 %0, %1, %2, %3;" : "=l"(r) : "l"(a), "l"(b), "l"(c)); return r;
}
__device__ __forceinline__ void upk2(uint64_t v, float& lo, float& hi) {
    asm("mov.b64 {%0, %1}, %2;" : "=f"(lo), "=f"(hi) : "l"(v));
}
__device__ __forceinline__ uint64_t bf2_to_f32x2(uint32_t q) {
    uint32_t lo = q << 16;
    uint32_t hi = q & 0xFFFF0000u;
    uint64_t r; asm("mov.b64 %0, {%1, %2};" : "=l"(r) : "r"(lo), "r"(hi)); return r;
}
__device__ __forceinline__ uint32_t pack_bf2(float lo, float hi) {
    uint32_t a = (uint32_t)__bfloat16_as_ushort(__float2bfloat16(lo));
    uint32_t b = (uint32_t)__bfloat16_as_ushort(__float2bfloat16(hi));
    return a | (b << 16);
}

// -------------------- fused KS-step core (8 cells/lane) --------------------
// x-neighbor exchange: 2 shuffles per ROW of 8 cells (halved per cell).
// y-exchange via double-buffered dynamic-smem rows, ONE barrier per step.
// Horizontals scalar FADD (pack-free), verticals aligned-pair f32x2.
// Masked cells written to 0 (== jnp.pad; also clears pre's ring -1 borders
// after step 1 in the first pass).
template<int KSv, bool MASKED>
__device__ __forceinline__ void steps_loop(
    float4 (&u)[2*RPT], const uint4 (&frq)[RPT],
    float* __restrict__ topP, float* __restrict__ botP,
    int lane, int ty, const bool (&mx)[8], const bool (&my)[RPT])
{
    const uint64_t Q2 = pk2(0.25f, 0.25f);

    #pragma unroll 1
    for (int s = 0; s < KSv; ++s) {
        const int p = s & 1;
        float* tp = topP + ((size_t)p * TPY + ty) * IX + 8 * lane;
        float* bp = botP + ((size_t)p * TPY + ty) * IX + 8 * lane;

        // publish this thread's top & bottom rows (pre-update state)
        *(float4*)(tp)     = u[0];
        *(float4*)(tp + 4) = u[1];
        *(float4*)(bp)     = u[2*RPT - 2];
        *(float4*)(bp + 4) = u[2*RPT - 1];
        __syncthreads();

        float4 z = make_float4(0.f, 0.f, 0.f, 0.f);
        float4 tA0 = z, tA1 = z, tB0 = z, tB1 = z;
        if (ty > 0) {
            const float* q = botP + ((size_t)p * TPY + (ty - 1)) * IX + 8 * lane;
            tA0 = *(const float4*)(q);
            tA1 = *(const float4*)(q + 4);
        }
        if (ty < TPY - 1) {
            const float* q = topP + ((size_t)p * TPY + (ty + 1)) * IX + 8 * lane;
            tB0 = *(const float4*)(q);
            tB1 = *(const float4*)(q + 4);
        }

        // in-place rolling update (old u[j+1] intact when used)
        float4 p0 = tA0, p1 = tA1;
        #pragma unroll
        for (int j = 0; j < RPT; ++j) {
            float4 a0 = u[2*j], a1 = u[2*j + 1];
            float4 b0 = (j < RPT - 1) ? u[2*j + 2] : tB0;
            float4 b1 = (j < RPT - 1) ? u[2*j + 3] : tB1;
            // x-neighbors across lanes (warp-edge self values -> tile ring 0,
            // tolerated: state k valid at rings >= k, outputs at rings >= 8)
            float lf = __shfl_up_sync(0xffffffffu, a1.w, 1);
            float rg = __shfl_down_sync(0xffffffffu, a0.x, 1);

            bool doit = !((ty == 0 && j == 0) || (ty == TPY - 1 && j == RPT - 1));
            if (doit) {
                // horizontals: scalar FADDs (fresh, pack-free)
                float h0 = lf   + a0.y;
                float h1 = a0.x + a0.z;
                float h2 = a0.y + a0.w;
                float h3 = a0.z + a1.x;
                float h4 = a0.w + a1.y;
                float h5 = a1.x + a1.z;
                float h6 = a1.y + a1.w;
                float h7 = a1.z + rg;
                // verticals: aligned float4 halves -> free packs
                uint64_t v01 = add2(pk2(p0.x, p0.y), pk2(b0.x, b0.y));
                uint64_t v23 = add2(pk2(p0.z, p0.w), pk2(b0.z, b0.w));
                uint64_t v45 = add2(pk2(p1.x, p1.y), pk2(b1.x, b1.y));
                uint64_t v67 = add2(pk2(p1.z, p1.w), pk2(b1.z, b1.w));
                uint64_t o01 = fma2(add2(v01, pk2(h0, h1)), Q2, bf2_to_f32x2(frq[j].x));
                uint64_t o23 = fma2(add2(v23, pk2(h2, h3)), Q2, bf2_to_f32x2(frq[j].y));
                uint64_t o45 = fma2(add2(v45, pk2(h4, h5)), Q2, bf2_to_f32x2(frq[j].z));
                uint64_t o67 = fma2(add2(v67, pk2(h6, h7)), Q2, bf2_to_f32x2(frq[j].w));
                float4 o0, o1;
                upk2(o01, o0.x, o0.y);
                upk2(o23, o0.z, o0.w);
                upk2(o45, o1.x, o1.y);
                upk2(o67, o1.z, o1.w);
                if (MASKED) {
                    if (!(my[j] && mx[0])) o0.x = 0.f;
                    if (!(my[j] && mx[1])) o0.y = 0.f;
                    if (!(my[j] && mx[2])) o0.z = 0.f;
                    if (!(my[j] && mx[3])) o0.w = 0.f;
                    if (!(my[j] && mx[4])) o1.x = 0.f;
                    if (!(my[j] && mx[5])) o1.y = 0.f;
                    if (!(my[j] && mx[6])) o1.z = 0.f;
                    if (!(my[j] && mx[7])) o1.w = 0.f;
                }
                u[2*j]     = o0;
                u[2*j + 1] = o1;
            }
            p0 = a0; p1 = a1;
        }
    }
}

// -------------------- generic fused pass (packed src + bf16 fq) --------------------
template<int KSv, int HXv, int HYv>
__global__ __launch_bounds__(NTHR, 2)
void jacobi_fused(const float* __restrict__ src,
                  const __nv_bfloat16* __restrict__ fq,
                  float* __restrict__ dst)
{
    constexpr int TXv  = IX - 2 * HXv;
    constexpr int TYv  = IY - 2 * HYv;
    constexpr int NBXv = (N + TXv - 1) / TXv;
    constexpr int NBYv = (N + TYv - 1) / TYv;

    extern __shared__ float smembuf[];
    float* topP = smembuf;
    float* botP = smembuf + 2 * TPY * IX;

    const int lane = threadIdx.x;
    const int ty   = threadIdx.y;
    const int bx = blockIdx.x, by = blockIdx.y, b = blockIdx.z;

    const int gx0 = bx * TXv - HXv;
    const int gy0 = by * TYv - HYv;
    const int iy0 = ty * RPT;
    const int gx  = gx0 + 8 * lane;        // multiple of 8

    const bool edge = (bx == 0) | (bx == NBXv - 1) | (by == 0) | (by == NBYv - 1);

    const float*         img  = src + (size_t)b * N * N;
    const __nv_bfloat16* fimg = fq  + (size_t)b * N * N;

    float4 u[2*RPT];
    uint4  frq[RPT];
    bool mx[8], my[RPT];
    #pragma unroll
    for (int l = 0; l < 8; ++l) {
        int x = gx + l;
        mx[l] = (x >= 0) && (x < N);
    }

    if (!edge) {
        #pragma unroll
        for (int j = 0; j < RPT; ++j) {
            int gy = gy0 + iy0 + j;
            my[j] = true;
            const float* r = img + (size_t)gy * N + gx;
            u[2*j]     = *(const float4*)(r);
            u[2*j + 1] = *(const float4*)(r + 4);
            frq[j]     = *(const uint4*)(fimg + (size_t)gy * N + gx);
        }
    } else {
        #pragma unroll
        for (int j = 0; j < RPT; ++j) {
            int gy = gy0 + iy0 + j;
            my[j] = (gy >= 0) && (gy < N);
            if (my[j] && gx >= 0 && gx <= N - 8) {
                const float* r = img + (size_t)gy * N + gx;
                u[2*j]     = *(const float4*)(r);
                u[2*j + 1] = *(const float4*)(r + 4);
                frq[j]     = *(const uint4*)(fimg + (size_t)gy * N + gx);
            } else {
                float t[8]; uint32_t bf[8];
                #pragma unroll
                for (int l = 0; l < 8; ++l) {
                    bool in = my[j] && mx[l];
                    t[l]  = in ? img[(size_t)gy * N + (gx + l)] : 0.f;
                    bf[l] = in ? (uint32_t)__bfloat16_as_ushort(fimg[(size_t)gy * N + (gx + l)]) : 0u;
                }
                u[2*j]     = make_float4(t[0], t[1], t[2], t[3]);
                u[2*j + 1] = make_float4(t[4], t[5], t[6], t[7]);
                frq[j] = make_uint4(bf[0] | (bf[1] << 16), bf[2] | (bf[3] << 16),
                                    bf[4] | (bf[5] << 16), bf[6] | (bf[7] << 16));
            }
        }
    }

    if (!edge) steps_loop<KSv, false>(u, frq, topP, botP, lane, ty, mx, my);
    else       steps_loop<KSv, true >(u, frq, topP, botP, lane, ty, mx, my);

    // store: ix in [HXv, HXv+TXv) -> lanes [HXv/8, (HXv+TXv)/8), whole-lane
    // in-grid test (gx multiple of 8)
    if (lane >= HXv / 8 && lane < (HXv + TXv) / 8 && gx >= 0 && gx <= N - 8) {
        float* dimg = dst + (size_t)b * N * N;
        #pragma unroll
        for (int j = 0; j < RPT; ++j) {
            int iy = iy0 + j;
            int gy = gy0 + iy;
            if (iy >= HYv && iy < HYv + TYv && gy < N) {
                float* r = dimg + (size_t)gy * N + gx;
                *(float4*)(r)     = u[2*j];
                *(float4*)(r + 4) = u[2*j + 1];
            }
        }
    }
}

// -------------------- first fused pass: iterations 1..8 from strided pre/f -------
__global__ __launch_bounds__(NTHR, 2)
void jacobi_first_fused(const float* __restrict__ pre,
                        const float* __restrict__ f,
                        float* __restrict__ dst,
                        __nv_bfloat16* __restrict__ fqout)
{
    extern __shared__ float smembuf[];
    float* topP = smembuf;
    float* botP = smembuf + 2 * TPY * IX;

    const int lane = threadIdx.x;
    const int ty   = threadIdx.y;
    const int bx = blockIdx.x, by = blockIdx.y, b = blockIdx.z;

    const int gx0 = bx * TXA - HXA;
    const int gy0 = by * TYA - HYA;
    const int iy0 = ty * RPT;
    const int gx  = gx0 + 8 * lane;

    const bool edge = (bx == 0) | (bx == NBXA - 1) | (by == 0) | (by == NBYA - 1);

    const float* preb = pre + (size_t)b * G * G;
    const float* fb   = f   + (size_t)b * G * G;

    float4 u[2*RPT];
    uint4  frq[RPT];
    bool mx[8], my[RPT];
    #pragma unroll
    for (int l = 0; l < 8; ++l) {
        int x = gx + l;
        mx[l] = (x >= 0) && (x < N);
    }

    #pragma unroll
    for (int j = 0; j < RPT; ++j) {
        int gy = gy0 + iy0 + j;
        my[j] = (gy >= 0) && (gy < N);
        if (!edge) {
            size_t c = (size_t)(gy + 1) * G + (gx + 1);
            float t[8]; uint32_t bf[8];
            #pragma unroll
            for (int l = 0; l < 8; ++l) {
                t[l]  = preb[c + l];
                float q = 0.25f * (H2 * fb[c + l]);
                bf[l] = (uint32_t)__bfloat16_as_ushort(__float2bfloat16(q));
            }
            u[2*j]     = make_float4(t[0], t[1], t[2], t[3]);
            u[2*j + 1] = make_float4(t[4], t[5], t[6], t[7]);
            frq[j] = make_uint4(bf[0] | (bf[1] << 16), bf[2] | (bf[3] << 16),
                                bf[4] | (bf[5] << 16), bf[6] | (bf[7] << 16));
        } else {
            bool py = (gy >= -1) && (gy <= N);   // pre ring -1..N valid
            float t[8]; uint32_t bf[8];
            #pragma unroll
            for (int l = 0; l < 8; ++l) {
                int x = gx + l;
                bool px = (x >= -1) && (x <= N);
                size_t c = (size_t)(gy + 1) * G + (x + 1);
                t[l] = (py && px) ? preb[c] : 0.f;   // real borders at ring -1/N
                float q = (my[j] && mx[l]) ? 0.25f * (H2 * fb[c]) : 0.f;
                bf[l] = (uint32_t)__bfloat16_as_ushort(__float2bfloat16(q));
            }
            u[2*j]     = make_float4(t[0], t[1], t[2], t[3]);
            u[2*j + 1] = make_float4(t[4], t[5], t[6], t[7]);
            frq[j] = make_uint4(bf[0] | (bf[1] << 16), bf[2] | (bf[3] << 16),
                                bf[4] | (bf[5] << 16), bf[6] | (bf[7] << 16));
        }
    }

    if (!edge) steps_loop<8, false>(u, frq, topP, botP, lane, ty, mx, my);
    else       steps_loop<8, true >(u, frq, topP, botP, lane, ty, mx, my);

    // store result (state 8) + packed fq for later passes
    if (lane >= HXA / 8 && lane < (HXA + TXA) / 8 && gx >= 0 && gx <= N - 8) {
        float*         dimg = dst   + (size_t)b * N * N;
        __nv_bfloat16* qimg = fqout + (size_t)b * N * N;
        #pragma unroll
        for (int j = 0; j < RPT; ++j) {
            int iy = iy0 + j;
            int gy = gy0 + iy;
            if (iy >= HYA && iy < HYA + TYA && gy < N) {
                float* r = dimg + (size_t)gy * N + gx;
                *(float4*)(r)     = u[2*j];
                *(float4*)(r + 4) = u[2*j + 1];
                *(uint4*)(qimg + (size_t)gy * N + gx) = frq[j];
            }
        }
    }
}

// -------------------- launch --------------------
extern "C" void kernel_launch(void* const* d_in, const int* in_sizes, int n_in,
                              void* d_out, int out_size)
{
    const float* pre = (const float*)d_in[0];
    const float* f   = (const float*)d_in[1];
    float* out = (float*)d_out;

    float*         w_ptr;
    __nv_bfloat16* fq_ptr;
    cudaGetSymbolAddress((void**)&w_ptr,  g_w);
    cudaGetSymbolAddress((void**)&fq_ptr, g_fq);

    cudaFuncSetAttribute(jacobi_first_fused,
                         cudaFuncAttributeMaxDynamicSharedMemorySize, SMEM_BYTES);
    cudaFuncSetAttribute(jacobi_fused<8, HXA, HYA>,
                         cudaFuncAttributeMaxDynamicSharedMemorySize, SMEM_BYTES);
    cudaFuncSetAttribute(jacobi_fused<2, 8, 2>,
                         cudaFuncAttributeMaxDynamicSharedMemorySize, SMEM_BYTES);

    dim3 blk(32, TPY, 1);

    // iterations 1..8: fused first pass (also packs fq)  pre,f -> out
    jacobi_first_fused<<<dim3(NBXA, NBYA, BSZ), blk, SMEM_BYTES>>>(pre, f, out, fq_ptr);

    // iterations 9..48: 5 heavy passes of 8 steps, ping-pong out <-> w
    const float* s = out;
    for (int p = 0; p < 5; ++p) {
        float* d = (p & 1) ? out : w_ptr;   // p0->w, p1->out, p2->w, p3->out, p4->w
        jacobi_fused<8, HXA, HYA><<<dim3(NBXA, NBYA, BSZ), blk, SMEM_BYTES>>>(s, fq_ptr, d);
        s = d;
    }

    // iterations 49..50: light 2-step fused tail, w -> out
    {
        constexpr int TXT  = IX - 2 * 8;    // 240
        constexpr int TYT  = IY - 2 * 2;    // 44
        constexpr int NBXT = (N + TXT - 1) / TXT;   // 9
        constexpr int NBYT = (N + TYT - 1) / TYT;   // 47
        jacobi_fused<2, 8, 2><<<dim3(NBXT, NBYT, BSZ), blk, SMEM_BYTES>>>(w_ptr, fq_ptr, out);
    }
}

// round 14
// speedup vs baseline: 1.9494x; 1.9494x over previous
#include <cuda_runtime.h>
#include <cuda_bf16.h>
#include <cstdint>

// Problem constants
#define G    2050
#define N    2048
#define BSZ  16
#define H2   (0.00048828125f * 0.00048828125f)   // 2^-22

// Block shape: one warp spans full tile width; 8 warp-bands of 12 rows
#define IX   128             // 32 lanes x float4
#define TPY  8
#define RPT  12              // rows per thread
#define IY   (TPY*RPT)       // 96
#define NTHR (32*TPY)        // 256

// Heavy-pass geometry
#define HXA  8
#define HYA  8
#define TXA  (IX - 2*HXA)    // 112
#define TYA  (IY - 2*HYA)    // 80
#define NBXA ((N + TXA - 1)/TXA)   // 19
#define NBYA ((N + TYA - 1)/TYA)   // 26

// Scratch (static device arrays; no runtime allocation)
__device__ float         g_w [(size_t)BSZ * N * N];
__device__ __nv_bfloat16 g_fq[(size_t)BSZ * N * N];   // bf16(h2 * f * 0.25)

// ---------------- packed f32x2 helpers (Blackwell) ----------------
__device__ __forceinline__ uint64_t pk2(float lo, float hi) {
    uint64_t r; asm("mov.b64 %0, {%1, %2};" : "=l"(r) : "f"(lo), "f"(hi)); return r;
}
__device__ __forceinline__ uint64_t add2(uint64_t a, uint64_t b) {
    uint64_t r; asm("add.rn.f32x2 %0, %1, %2;" : "=l"(r) : "l"(a), "l"(b)); return r;
}
__device__ __forceinline__ uint64_t fma2(uint64_t a, uint64_t b, uint64_t c) {
    uint64_t r; asm("fma.rn.f32x2 %0, %1, %2, %3;" : "=l"(r) : "l"(a), "l"(b), "l"(c)); return r;
}
__device__ __forceinline__ void upk2(uint64_t v, float& lo, float& hi) {
    asm("mov.b64 {%0, %1}, %2;" : "=f"(lo), "=f"(hi) : "l"(v));
}
// bf16x2 (packed in u32) -> f32x2 (u64)
__device__ __forceinline__ uint64_t bf2_to_f32x2(uint32_t q) {
    uint32_t lo = q << 16;
    uint32_t hi = q & 0xFFFF0000u;
    uint64_t r; asm("mov.b64 %0, {%1, %2};" : "=l"(r) : "r"(lo), "r"(hi)); return r;
}
__device__ __forceinline__ uint32_t pack_bf2(float lo, float hi) {
    uint32_t a = (uint32_t)__bfloat16_as_ushort(__float2bfloat16(lo));
    uint32_t b = (uint32_t)__bfloat16_as_ushort(__float2bfloat16(hi));
    return a | (b << 16);
}

// -------------------- fused KS-step core --------------------
// x-neighbor exchange via warp shuffles; y-exchange via double-buffered smem
// rows with ONE barrier per step. Horizontals as scalar FADDs (pack-free),
// verticals as aligned-pair f32x2 — zero cross-pair MOVs.
// Masked (out-of-grid) cells are written to 0 every step (== jnp.pad zeros;
// also clears pre's ring -1 borders after step 1 in the first pass).
template<int KSv, bool MASKED>
__device__ __forceinline__ void steps_loop(
    float4 (&u)[RPT], const uint2 (&frq)[RPT],
    float (&topP)[2][TPY][IX], float (&botP)[2][TPY][IX],
    int lane, int ty, const bool (&mx)[4], const bool (&my)[RPT])
{
    const uint64_t Q2 = pk2(0.25f, 0.25f);

    #pragma unroll 1
    for (int s = 0; s < KSv; ++s) {
        const int p = s & 1;

        // publish this thread's top & bottom rows (pre-update state)
        *(float4*)(&topP[p][ty][4 * lane]) = u[0];
        *(float4*)(&botP[p][ty][4 * lane]) = u[RPT - 1];
        __syncthreads();

        float4 tA = make_float4(0.f, 0.f, 0.f, 0.f);
        float4 tB = make_float4(0.f, 0.f, 0.f, 0.f);
        if (ty > 0)       tA = *(const float4*)(&botP[p][ty - 1][4 * lane]);
        if (ty < TPY - 1) tB = *(const float4*)(&topP[p][ty + 1][4 * lane]);

        // in-place rolling update (old u[j+1] intact when used)
        float4 prev = tA;
        #pragma unroll
        for (int j = 0; j < RPT; ++j) {
            float4 curo = u[j];
            float4 belo = (j < RPT - 1) ? u[j + 1] : tB;
            // x-neighbors across lanes (warp-edge self values -> tile ring 0,
            // tolerated: state k valid at rings >= k, outputs at rings >= halo)
            float lf = __shfl_up_sync(0xffffffffu, curo.w, 1);
            float rg = __shfl_down_sync(0xffffffffu, curo.x, 1);

            bool doit = !((ty == 0 && j == 0) || (ty == TPY - 1 && j == RPT - 1));
            if (doit) {
                // horizontals: scalar FADDs (results packed pair-adjacent, free)
                float h0 = lf     + curo.y;
                float h1 = curo.x + curo.z;
                float h2 = curo.y + curo.w;
                float h3 = curo.z + rg;
                // verticals: aligned float4 halves -> free packs
                uint64_t v01 = add2(pk2(prev.x, prev.y), pk2(belo.x, belo.y));
                uint64_t v23 = add2(pk2(prev.z, prev.w), pk2(belo.z, belo.w));
                uint64_t o01 = fma2(add2(v01, pk2(h0, h1)), Q2, bf2_to_f32x2(frq[j].x));
                uint64_t o23 = fma2(add2(v23, pk2(h2, h3)), Q2, bf2_to_f32x2(frq[j].y));
                float4 o;
                upk2(o01, o.x, o.y);
                upk2(o23, o.z, o.w);
                if (MASKED) {
                    // out-of-grid cells become/stay 0 => matches jnp.pad
                    if (!(my[j] && mx[0])) o.x = 0.f;
                    if (!(my[j] && mx[1])) o.y = 0.f;
                    if (!(my[j] && mx[2])) o.z = 0.f;
                    if (!(my[j] && mx[3])) o.w = 0.f;
                }
                u[j] = o;
            }
            prev = curo;
        }
    }
}

// -------------------- generic fused pass (packed src + bf16 fq) --------------------
template<int KSv, int HXv, int HYv>
__global__ __launch_bounds__(NTHR, 2)
void jacobi_fused(const float* __restrict__ src,
                  const __nv_bfloat16* __restrict__ fq,
                  float* __restrict__ dst)
{
    constexpr int TXv  = IX - 2 * HXv;
    constexpr int TYv  = IY - 2 * HYv;
    constexpr int NBXv = (N + TXv - 1) / TXv;
    constexpr int NBYv = (N + TYv - 1) / TYv;

    __shared__ float topP[2][TPY][IX];
    __shared__ float botP[2][TPY][IX];

    const int lane = threadIdx.x;
    const int ty   = threadIdx.y;
    const int bx = blockIdx.x, by = blockIdx.y, b = blockIdx.z;

    const int gx0 = bx * TXv - HXv;
    const int gy0 = by * TYv - HYv;
    const int iy0 = ty * RPT;
    const int gx  = gx0 + 4 * lane;        // multiple of 4

    const bool edge = (bx == 0) | (bx == NBXv - 1) | (by == 0) | (by == NBYv - 1);

    const float*         img  = src + (size_t)b * N * N;
    const __nv_bfloat16* fimg = fq  + (size_t)b * N * N;

    float4 u[RPT];
    uint2  frq[RPT];
    bool mx[4], my[RPT];
    #pragma unroll
    for (int l = 0; l < 4; ++l) {
        int x = gx + l;
        mx[l] = (x >= 0) && (x < N);
    }

    if (!edge) {
        #pragma unroll
        for (int j = 0; j < RPT; ++j) {
            int gy = gy0 + iy0 + j;
            my[j]  = true;
            u[j]   = *(const float4*)(img + (size_t)gy * N + gx);
            frq[j] = *(const uint2*)(fimg + (size_t)gy * N + gx);
        }
    } else {
        #pragma unroll
        for (int j = 0; j < RPT; ++j) {
            int gy = gy0 + iy0 + j;
            my[j] = (gy >= 0) && (gy < N);
            if (my[j] && gx >= 0 && gx <= N - 4) {
                u[j]   = *(const float4*)(img + (size_t)gy * N + gx);
                frq[j] = *(const uint2*)(fimg + (size_t)gy * N + gx);
            } else {
                float t[4]; uint32_t bf[4];
                #pragma unroll
                for (int l = 0; l < 4; ++l) {
                    bool in = my[j] && mx[l];
                    t[l]  = in ? img[(size_t)gy * N + (gx + l)] : 0.f;
                    bf[l] = in ? (uint32_t)__bfloat16_as_ushort(fimg[(size_t)gy * N + (gx + l)]) : 0u;
                }
                u[j]   = make_float4(t[0], t[1], t[2], t[3]);
                frq[j] = make_uint2(bf[0] | (bf[1] << 16), bf[2] | (bf[3] << 16));
            }
        }
    }

    if (!edge) steps_loop<KSv, false>(u, frq, topP, botP, lane, ty, mx, my);
    else       steps_loop<KSv, true >(u, frq, topP, botP, lane, ty, mx, my);

    if (lane >= HXv / 4 && lane < (HXv + TXv) / 4 && gx >= 0 && gx <= N - 4) {
        float* dimg = dst + (size_t)b * N * N;
        #pragma unroll
        for (int j = 0; j < RPT; ++j) {
            int iy = iy0 + j;
            int gy = gy0 + iy;
            if (iy >= HYv && iy < HYv + TYv && gy < N) {
                *(float4*)(dimg + (size_t)gy * N + gx) = u[j];
            }
        }
    }
}

// -------------------- first fused pass: iterations 1..8 from strided pre/f -------
// Loads pre/f (stride G, incl. ring -1 = real borders, used by step 1), packs
// fq = bf16(0.25*h2*f) as side output, runs the same 8-step engine.
__global__ __launch_bounds__(NTHR, 2)
void jacobi_first_fused(const float* __restrict__ pre,
                        const float* __restrict__ f,
                        float* __restrict__ dst,
                        __nv_bfloat16* __restrict__ fqout)
{
    __shared__ float topP[2][TPY][IX];
    __shared__ float botP[2][TPY][IX];

    const int lane = threadIdx.x;
    const int ty   = threadIdx.y;
    const int bx = blockIdx.x, by = blockIdx.y, b = blockIdx.z;

    const int gx0 = bx * TXA - HXA;
    const int gy0 = by * TYA - HYA;
    const int iy0 = ty * RPT;
    const int gx  = gx0 + 4 * lane;

    const bool edge = (bx == 0) | (bx == NBXA - 1) | (by == 0) | (by == NBYA - 1);

    const float* preb = pre + (size_t)b * G * G;
    const float* fb   = f   + (size_t)b * G * G;

    float4 u[RPT];
    uint2  frq[RPT];
    bool mx[4], my[RPT];
    #pragma unroll
    for (int l = 0; l < 4; ++l) {
        int x = gx + l;
        mx[l] = (x >= 0) && (x < N);
    }

    if (!edge) {
        // all coords strictly inside the grid
        #pragma unroll
        for (int j = 0; j < RPT; ++j) {
            int gy = gy0 + iy0 + j;
            my[j] = true;
            size_t c = (size_t)(gy + 1) * G + (gx + 1);
            float t0 = preb[c + 0], t1 = preb[c + 1], t2 = preb[c + 2], t3 = preb[c + 3];
            float q0 = 0.25f * (H2 * fb[c + 0]);
            float q1 = 0.25f * (H2 * fb[c + 1]);
            float q2 = 0.25f * (H2 * fb[c + 2]);
            float q3 = 0.25f * (H2 * fb[c + 3]);
            u[j]   = make_float4(t0, t1, t2, t3);
            frq[j] = make_uint2(pack_bf2(q0, q1), pack_bf2(q2, q3));
        }
    } else {
        #pragma unroll
        for (int j = 0; j < RPT; ++j) {
            int gy = gy0 + iy0 + j;
            my[j] = (gy >= 0) && (gy < N);
            bool py = (gy >= -1) && (gy <= N);   // pre ring -1..N valid
            float t[4]; uint32_t bf[4];
            #pragma unroll
            for (int l = 0; l < 4; ++l) {
                int x = gx + l;
                bool px = (x >= -1) && (x <= N);
                size_t c = (size_t)(gy + 1) * G + (x + 1);
                t[l] = (py && px) ? preb[c] : 0.f;   // real borders at ring -1/N
                float q = (my[j] && mx[l]) ? 0.25f * (H2 * fb[c]) : 0.f;
                bf[l] = (uint32_t)__bfloat16_as_ushort(__float2bfloat16(q));
            }
            u[j]   = make_float4(t[0], t[1], t[2], t[3]);
            frq[j] = make_uint2(bf[0] | (bf[1] << 16), bf[2] | (bf[3] << 16));
        }
    }

    if (!edge) steps_loop<8, false>(u, frq, topP, botP, lane, ty, mx, my);
    else       steps_loop<8, true >(u, frq, topP, botP, lane, ty, mx, my);

    // store result (state 8) + packed fq for later passes
    if (lane >= HXA / 4 && lane < (HXA + TXA) / 4 && gx >= 0 && gx <= N - 4) {
        float*         dimg = dst   + (size_t)b * N * N;
        __nv_bfloat16* qimg = fqout + (size_t)b * N * N;
        #pragma unroll
        for (int j = 0; j < RPT; ++j) {
            int iy = iy0 + j;
            int gy = gy0 + iy;
            if (iy >= HYA && iy < HYA + TYA && gy < N) {
                *(float4*)(dimg + (size_t)gy * N + gx) = u[j];
                *(uint2*)(qimg + (size_t)gy * N + gx)  = frq[j];
            }
        }
    }
}

// -------------------- launch --------------------
extern "C" void kernel_launch(void* const* d_in, const int* in_sizes, int n_in,
                              void* d_out, int out_size)
{
    const float* pre = (const float*)d_in[0];
    const float* f   = (const float*)d_in[1];
    float* out = (float*)d_out;

    float*         w_ptr;
    __nv_bfloat16* fq_ptr;
    cudaGetSymbolAddress((void**)&w_ptr,  g_w);
    cudaGetSymbolAddress((void**)&fq_ptr, g_fq);

    dim3 blk(32, TPY, 1);

    // iterations 1..8: fused first pass (also packs fq)  pre,f -> out
    jacobi_first_fused<<<dim3(NBXA, NBYA, BSZ), blk>>>(pre, f, out, fq_ptr);

    // iterations 9..48: 5 heavy passes of 8 steps, ping-pong out <-> w
    const float* s = out;
    for (int p = 0; p < 5; ++p) {
        float* d = (p & 1) ? out : w_ptr;   // p0->w, p1->out, p2->w, p3->out, p4->w
        jacobi_fused<8, HXA, HYA><<<dim3(NBXA, NBYA, BSZ), blk>>>(s, fq_ptr, d);
        s = d;
    }

    // iterations 49..50: light 2-step fused tail, w -> out
    {
        constexpr int TXT  = IX - 2 * 4;    // 120
        constexpr int TYT  = IY - 2 * 2;    // 92
        constexpr int NBXT = (N + TXT - 1) / TXT;   // 18
        constexpr int NBYT = (N + TYT - 1) / TYT;   // 23
        jacobi_fused<2, 4, 2><<<dim3(NBXT, NBYT, BSZ), blk>>>(w_ptr, fq_ptr, out);
    }
}